// round 2
// baseline (speedup 1.0000x reference)
#include <cuda_runtime.h>
#include <cuda_bf16.h>

// Problem-fixed capacities (N=100000, E=1600000 per setup_inputs)
#define NMAX   100000
#define EMAX   1600000
#define ETOTMX (NMAX + EMAX)

// ---------------- scratch (static device globals; no allocation) -------------
__device__ __align__(16) float g_h1  [NMAX * 32];   // layer1 projected features
__device__ __align__(16) float g_as1 [NMAX * 4];
__device__ __align__(16) float g_ad1 [NMAX * 4];
__device__ __align__(16) float g_s1  [NMAX * 4];    // softmax denominators
__device__ __align__(16) float g_acc1[NMAX * 32];   // layer1 attention output -> ELU in place
__device__ __align__(16) float g_h2  [NMAX * 64];
__device__ __align__(16) float g_as2 [NMAX * 8];
__device__ __align__(16) float g_ad2 [NMAX * 8];
__device__ __align__(16) float g_s2  [NMAX * 8];
__device__ __align__(16) float g_acc2[NMAX * 64];
__device__ __align__(16) float g_p   [ETOTMX * 8];  // per-edge exp(score); reused both layers

// vector global reduction (sm_90+): 4 floats in one L2 atomic transaction
__device__ __forceinline__ void red_add_v4(float* addr, float4 v) {
    asm volatile("red.global.add.v4.f32 [%0], {%1, %2, %3, %4};"
                 :: "l"(addr), "f"(v.x), "f"(v.y), "f"(v.z), "f"(v.w)
                 : "memory");
}

__device__ __forceinline__ float lrelu(float t) { return t > 0.f ? t : 0.2f * t; }
__device__ __forceinline__ float elu(float t)   { return t > 0.f ? t : expm1f(t); }

// ---------------- zero accumulators ------------------------------------------
__global__ void k_zero(int N) {
    int i = blockIdx.x * blockDim.x + threadIdx.x;
    int stride = gridDim.x * blockDim.x;
    for (int j = i; j < N * 4;  j += stride) g_s1[j]   = 0.f;
    for (int j = i; j < N * 8;  j += stride) g_s2[j]   = 0.f;
    for (int j = i; j < N * 32; j += stride) g_acc1[j] = 0.f;
    for (int j = i; j < N * 64; j += stride) g_acc2[j] = 0.f;
}

// ---------------- layer 1: node-side (rank-1 projection) ---------------------
__global__ void k_l1_node(const float* __restrict__ x, const float* __restrict__ W1,
                          const float* __restrict__ atts, const float* __restrict__ attd,
                          int N) {
    int i = blockIdx.x * blockDim.x + threadIdx.x;
    if (i >= N) return;
    float xv = x[i];
#pragma unroll
    for (int hd = 0; hd < 4; hd++) {
        float cs = 0.f, cd = 0.f;
#pragma unroll
        for (int c = 0; c < 8; c++) {
            float w = __ldg(&W1[hd * 8 + c]);
            g_h1[i * 32 + hd * 8 + c] = xv * w;
            cs += w * __ldg(&atts[hd * 8 + c]);
            cd += w * __ldg(&attd[hd * 8 + c]);
        }
        g_as1[i * 4 + hd] = xv * cs;
        g_ad1[i * 4 + hd] = xv * cd;
    }
}

// ---------------- layer 1: edge pass A (p = exp(leakyrelu), sum into s) ------
__global__ void k_l1_edgeA(const int* __restrict__ src, const int* __restrict__ dst,
                           int E, int Etot) {
    int e = blockIdx.x * blockDim.x + threadIdx.x;
    if (e >= Etot) return;
    int s, d;
    if (e < E) { s = src[e]; d = dst[e]; } else { s = d = e - E; }
    float4 as = *(const float4*)&g_as1[s * 4];
    float4 ad = *(const float4*)&g_ad1[d * 4];
    float4 p;
    p.x = __expf(lrelu(as.x + ad.x));
    p.y = __expf(lrelu(as.y + ad.y));
    p.z = __expf(lrelu(as.z + ad.z));
    p.w = __expf(lrelu(as.w + ad.w));
    *(float4*)&g_p[e * 4] = p;
    red_add_v4(&g_s1[d * 4], p);
}

// ---------------- layer 1: edge pass B (scatter alpha * h[src]) --------------
// 8 threads per edge, each handles 4 contiguous channels (float4)
__global__ void k_l1_edgeB(const int* __restrict__ src, const int* __restrict__ dst,
                           int E, int Etot) {
    int tid = blockIdx.x * blockDim.x + threadIdx.x;
    int e = tid >> 3;
    if (e >= Etot) return;
    int l = tid & 7;
    int s, d;
    if (e < E) { s = src[e]; d = dst[e]; } else { s = d = e - E; }
    int hd = l >> 1;
    float p    = g_p[e * 4 + hd];
    float sden = g_s1[d * 4 + hd];
    float a    = p / (sden + 1e-16f);
    float4 hv = *(const float4*)&g_h1[s * 32 + l * 4];
    float4 m  = make_float4(a * hv.x, a * hv.y, a * hv.z, a * hv.w);
    red_add_v4(&g_acc1[d * 32 + l * 4], m);
}

// ---------------- layer 1: bias + ELU (in place) ------------------------------
__global__ void k_l1_fin(const float* __restrict__ bias, int N) {
    int i = blockIdx.x * blockDim.x + threadIdx.x;
    if (i >= N * 32) return;
    float v = g_acc1[i] + __ldg(&bias[i & 31]);
    g_acc1[i] = elu(v);
}

// ---------------- layer 2: h2 = act1 @ W2 (32 -> 64) -------------------------
__global__ void k_l2_h2(const float* __restrict__ W2, int N) {
    int t = blockIdx.x * blockDim.x + threadIdx.x;
    if (t >= N * 64) return;
    int i = t >> 6, col = t & 63;
    float acc = 0.f;
#pragma unroll
    for (int k = 0; k < 32; k++)
        acc += g_acc1[i * 32 + k] * __ldg(&W2[k * 64 + col]);
    g_h2[t] = acc;
}

// ---------------- layer 2: attention coefficients ----------------------------
__global__ void k_l2_att(const float* __restrict__ atts, const float* __restrict__ attd,
                         int N) {
    int t = blockIdx.x * blockDim.x + threadIdx.x;
    if (t >= N * 8) return;
    int i = t >> 3, hd = t & 7;
    float cs = 0.f, cd = 0.f;
#pragma unroll
    for (int c = 0; c < 8; c++) {
        float hv = g_h2[i * 64 + hd * 8 + c];
        cs += hv * __ldg(&atts[hd * 8 + c]);
        cd += hv * __ldg(&attd[hd * 8 + c]);
    }
    g_as2[t] = cs;
    g_ad2[t] = cd;
}

// ---------------- layer 2: edge pass A ---------------------------------------
__global__ void k_l2_edgeA(const int* __restrict__ src, const int* __restrict__ dst,
                           int E, int Etot) {
    int e = blockIdx.x * blockDim.x + threadIdx.x;
    if (e >= Etot) return;
    int s, d;
    if (e < E) { s = src[e]; d = dst[e]; } else { s = d = e - E; }
    float4 as0 = *(const float4*)&g_as2[s * 8];
    float4 as1 = *(const float4*)&g_as2[s * 8 + 4];
    float4 ad0 = *(const float4*)&g_ad2[d * 8];
    float4 ad1 = *(const float4*)&g_ad2[d * 8 + 4];
    float4 p0, p1;
    p0.x = __expf(lrelu(as0.x + ad0.x));
    p0.y = __expf(lrelu(as0.y + ad0.y));
    p0.z = __expf(lrelu(as0.z + ad0.z));
    p0.w = __expf(lrelu(as0.w + ad0.w));
    p1.x = __expf(lrelu(as1.x + ad1.x));
    p1.y = __expf(lrelu(as1.y + ad1.y));
    p1.z = __expf(lrelu(as1.z + ad1.z));
    p1.w = __expf(lrelu(as1.w + ad1.w));
    *(float4*)&g_p[e * 8]     = p0;
    *(float4*)&g_p[e * 8 + 4] = p1;
    red_add_v4(&g_s2[d * 8],     p0);
    red_add_v4(&g_s2[d * 8 + 4], p1);
}

// ---------------- layer 2: edge pass B (16 threads/edge, 4 ch each) ----------
__global__ void k_l2_edgeB(const int* __restrict__ src, const int* __restrict__ dst,
                           int E, int Etot) {
    int tid = blockIdx.x * blockDim.x + threadIdx.x;
    int e = tid >> 4;
    if (e >= Etot) return;
    int l = tid & 15;
    int s, d;
    if (e < E) { s = src[e]; d = dst[e]; } else { s = d = e - E; }
    int hd = l >> 1;
    float p    = g_p[e * 8 + hd];
    float sden = g_s2[d * 8 + hd];
    float a    = p / (sden + 1e-16f);
    float4 hv = *(const float4*)&g_h2[s * 64 + l * 4];
    float4 m  = make_float4(a * hv.x, a * hv.y, a * hv.z, a * hv.w);
    red_add_v4(&g_acc2[d * 64 + l * 4], m);
}

// ---------------- layer 2 finalize + FC (warp per node) ----------------------
__global__ void k_fin_fc(const float* __restrict__ bias2, const float* __restrict__ fcw,
                         const float* __restrict__ fcb, float* __restrict__ out, int N) {
    int t = blockIdx.x * blockDim.x + threadIdx.x;
    int i = t >> 5;
    if (i >= N) return;
    int lane = t & 31;
    int c = lane * 2;
    float2 v = *(const float2*)&g_acc2[i * 64 + c];
    float e0 = elu(v.x + __ldg(&bias2[c]));
    float e1 = elu(v.y + __ldg(&bias2[c + 1]));
    float part = e0 * __ldg(&fcw[c]) + e1 * __ldg(&fcw[c + 1]);
#pragma unroll
    for (int o = 16; o > 0; o >>= 1)
        part += __shfl_xor_sync(0xffffffffu, part, o);
    if (lane == 0) out[i] = part + __ldg(&fcb[0]);
}

// ---------------- launch ------------------------------------------------------
extern "C" void kernel_launch(void* const* d_in, const int* in_sizes, int n_in,
                              void* d_out, int out_size) {
    const float* x    = (const float*)d_in[0];
    const int*   ei   = (const int*)  d_in[1];
    const float* W1   = (const float*)d_in[2];
    const float* as1  = (const float*)d_in[3];
    const float* ad1  = (const float*)d_in[4];
    const float* b1   = (const float*)d_in[5];
    const float* W2   = (const float*)d_in[6];
    const float* as2  = (const float*)d_in[7];
    const float* ad2  = (const float*)d_in[8];
    const float* b2   = (const float*)d_in[9];
    const float* fcw  = (const float*)d_in[10];
    const float* fcb  = (const float*)d_in[11];
    float* out = (float*)d_out;

    int N = in_sizes[0];          // x is [N, 1]
    int E = in_sizes[1] / 2;      // edge_index is [2, E]
    int Etot = E + N;             // + self loops
    const int* src = ei;
    const int* dst = ei + E;

    const int T = 256;
    k_zero   <<<1024, T>>>(N);
    k_l1_node<<<(N + T - 1) / T, T>>>(x, W1, as1, ad1, N);
    k_l1_edgeA<<<(Etot + T - 1) / T, T>>>(src, dst, E, Etot);
    k_l1_edgeB<<<((long)Etot * 8 + T - 1) / T, T>>>(src, dst, E, Etot);
    k_l1_fin <<<(N * 32 + T - 1) / T, T>>>(b1, N);
    k_l2_h2  <<<(N * 64 + T - 1) / T, T>>>(W2, N);
    k_l2_att <<<(N * 8 + T - 1) / T, T>>>(as2, ad2, N);
    k_l2_edgeA<<<(Etot + T - 1) / T, T>>>(src, dst, E, Etot);
    k_l2_edgeB<<<((long)Etot * 16 + T - 1) / T, T>>>(src, dst, E, Etot);
    k_fin_fc <<<((long)N * 32 + T - 1) / T, T>>>(b2, fcw, fcb, out, N);
}

// round 3
// speedup vs baseline: 1.4447x; 1.4447x over previous
#include <cuda_runtime.h>
#include <cuda_bf16.h>

// Problem-fixed capacities (N=100000, E=1600000 per setup_inputs)
#define NMAX   100000
#define EMAX   1600000
#define ETOTMX (NMAX + EMAX)
#define EPS    1e-16f

// ---------------- scratch (static device globals; no allocation) -------------
__device__ __align__(16) float g_as1 [NMAX * 4];
__device__ __align__(16) float g_ad1 [NMAX * 4];
__device__ __align__(16) float g_s1  [NMAX * 4];    // softmax denominators L1
__device__ __align__(16) float g_t1  [NMAX * 4];    // sum p * x[src] per head (rank-1 trick)
__device__ __align__(16) float g_act1[NMAX * 32];   // elu(layer1 out)
__device__ __align__(16) float g_h2  [NMAX * 64];
__device__ __align__(16) float g_as2 [NMAX * 8];
__device__ __align__(16) float g_ad2 [NMAX * 8];
__device__ __align__(16) float g_s2  [NMAX * 8];
__device__ __align__(16) float g_acc2[NMAX * 64];   // unnormalized sum p * h2[src]

// vector global reduction (sm_90+): 4 floats in one L2 transaction
__device__ __forceinline__ void red_add_v4(float* addr, float4 v) {
    asm volatile("red.global.add.v4.f32 [%0], {%1, %2, %3, %4};"
                 :: "l"(addr), "f"(v.x), "f"(v.y), "f"(v.z), "f"(v.w)
                 : "memory");
}
__device__ __forceinline__ void red_add_f32(float* addr, float v) {
    asm volatile("red.global.add.f32 [%0], %1;" :: "l"(addr), "f"(v) : "memory");
}

__device__ __forceinline__ float lrelu(float t) { return t > 0.f ? t : 0.2f * t; }
__device__ __forceinline__ float elu(float t)   { return t > 0.f ? t : expm1f(t); }

// ---------------- zero accumulators ------------------------------------------
__global__ void k_zero(int N) {
    int i = blockIdx.x * blockDim.x + threadIdx.x;
    int stride = gridDim.x * blockDim.x;
    for (int j = i; j < N * 4;  j += stride) { g_s1[j] = 0.f; g_t1[j] = 0.f; }
    for (int j = i; j < N * 8;  j += stride) g_s2[j]   = 0.f;
    for (int j = i; j < N * 64; j += stride) g_acc2[j] = 0.f;
}

// ---------------- layer 1: node-side attention coefficients ------------------
// h1[i] = x[i] * W1 (rank-1), so a_s[i][hd] = x[i] * (W1[hd]·att_src[hd])
__global__ void k_l1_node(const float* __restrict__ x, const float* __restrict__ W1,
                          const float* __restrict__ atts, const float* __restrict__ attd,
                          int N) {
    int i = blockIdx.x * blockDim.x + threadIdx.x;
    if (i >= N) return;
    float xv = x[i];
    float4 vs, vd;
    float* ps = &vs.x;
    float* pd = &vd.x;
#pragma unroll
    for (int hd = 0; hd < 4; hd++) {
        float cs = 0.f, cd = 0.f;
#pragma unroll
        for (int c = 0; c < 8; c++) {
            float w = __ldg(&W1[hd * 8 + c]);
            cs += w * __ldg(&atts[hd * 8 + c]);
            cd += w * __ldg(&attd[hd * 8 + c]);
        }
        ps[hd] = xv * cs;
        pd[hd] = xv * cd;
    }
    *(float4*)&g_as1[i * 4] = vs;
    *(float4*)&g_ad1[i * 4] = vd;
}

// ---------------- layer 1: single fused edge pass -----------------------------
// scatter p into s1 and p*x[src] into t1 (normalization deferred to finalize)
__global__ void k_l1_edge(const float* __restrict__ x,
                          const int* __restrict__ src, const int* __restrict__ dst,
                          int E, int Etot) {
    int e = blockIdx.x * blockDim.x + threadIdx.x;
    if (e >= Etot) return;
    int s, d;
    if (e < E) { s = src[e]; d = dst[e]; } else { s = d = e - E; }
    float4 as = *(const float4*)&g_as1[s * 4];
    float4 ad = *(const float4*)&g_ad1[d * 4];
    float xs = x[s];
    float4 p;
    p.x = __expf(lrelu(as.x + ad.x));
    p.y = __expf(lrelu(as.y + ad.y));
    p.z = __expf(lrelu(as.z + ad.z));
    p.w = __expf(lrelu(as.w + ad.w));
    red_add_v4(&g_s1[d * 4], p);
    float4 t = make_float4(p.x * xs, p.y * xs, p.z * xs, p.w * xs);
    red_add_v4(&g_t1[d * 4], t);
}

// ---------------- layer 1 finalize: normalize, project, bias, ELU -------------
__global__ void k_l1_fin(const float* __restrict__ W1, const float* __restrict__ bias,
                         int N) {
    int t = blockIdx.x * blockDim.x + threadIdx.x;
    if (t >= N * 32) return;
    int i = t >> 5, k = t & 31, hd = k >> 3;
    float sden = g_s1[i * 4 + hd];
    float num  = g_t1[i * 4 + hd];
    float v = num / (sden + EPS) * __ldg(&W1[k]) + __ldg(&bias[k]);
    g_act1[t] = elu(v);
}

// ---------------- layer 2: h2 = act1 @ W2 (32 -> 64) -------------------------
__global__ void k_l2_h2(const float* __restrict__ W2, int N) {
    int t = blockIdx.x * blockDim.x + threadIdx.x;
    if (t >= N * 64) return;
    int i = t >> 6, col = t & 63;
    float acc = 0.f;
#pragma unroll
    for (int k = 0; k < 32; k++)
        acc += g_act1[i * 32 + k] * __ldg(&W2[k * 64 + col]);
    g_h2[t] = acc;
}

// ---------------- layer 2: attention coefficients ----------------------------
__global__ void k_l2_att(const float* __restrict__ atts, const float* __restrict__ attd,
                         int N) {
    int t = blockIdx.x * blockDim.x + threadIdx.x;
    if (t >= N * 8) return;
    int i = t >> 3, hd = t & 7;
    float cs = 0.f, cd = 0.f;
#pragma unroll
    for (int c = 0; c < 8; c++) {
        float hv = g_h2[i * 64 + hd * 8 + c];
        cs += hv * __ldg(&atts[hd * 8 + c]);
        cd += hv * __ldg(&attd[hd * 8 + c]);
    }
    g_as2[t] = cs;
    g_ad2[t] = cd;
}

// ---------------- layer 2: single fused edge pass -----------------------------
// 8 threads per edge, one head each: scatter p into s2 and p*h2[src] into acc2
__global__ void k_l2_edge(const int* __restrict__ src, const int* __restrict__ dst,
                          int E, int Etot) {
    int tid = blockIdx.x * blockDim.x + threadIdx.x;
    int e = tid >> 3;
    if (e >= Etot) return;
    int hd = tid & 7;
    int s, d;
    if (e < E) { s = src[e]; d = dst[e]; } else { s = d = e - E; }
    float as = g_as2[s * 8 + hd];
    float ad = g_ad2[d * 8 + hd];
    float p = __expf(lrelu(as + ad));
    red_add_f32(&g_s2[d * 8 + hd], p);
    float4 h0 = *(const float4*)&g_h2[s * 64 + hd * 8];
    float4 h1 = *(const float4*)&g_h2[s * 64 + hd * 8 + 4];
    float4 m0 = make_float4(p * h0.x, p * h0.y, p * h0.z, p * h0.w);
    float4 m1 = make_float4(p * h1.x, p * h1.y, p * h1.z, p * h1.w);
    red_add_v4(&g_acc2[d * 64 + hd * 8],     m0);
    red_add_v4(&g_acc2[d * 64 + hd * 8 + 4], m1);
}

// ---------------- layer 2 finalize + FC (warp per node) ----------------------
__global__ void k_fin_fc(const float* __restrict__ bias2, const float* __restrict__ fcw,
                         const float* __restrict__ fcb, float* __restrict__ out, int N) {
    int t = blockIdx.x * blockDim.x + threadIdx.x;
    int i = t >> 5;
    if (i >= N) return;
    int lane = t & 31;
    int c = lane * 2;            // two adjacent channels, same head
    int hd = c >> 3;
    float inv = 1.f / (g_s2[i * 8 + hd] + EPS);
    float2 v = *(const float2*)&g_acc2[i * 64 + c];
    float e0 = elu(v.x * inv + __ldg(&bias2[c]));
    float e1 = elu(v.y * inv + __ldg(&bias2[c + 1]));
    float part = e0 * __ldg(&fcw[c]) + e1 * __ldg(&fcw[c + 1]);
#pragma unroll
    for (int o = 16; o > 0; o >>= 1)
        part += __shfl_xor_sync(0xffffffffu, part, o);
    if (lane == 0) out[i] = part + __ldg(&fcb[0]);
}

// ---------------- launch ------------------------------------------------------
extern "C" void kernel_launch(void* const* d_in, const int* in_sizes, int n_in,
                              void* d_out, int out_size) {
    const float* x    = (const float*)d_in[0];
    const int*   ei   = (const int*)  d_in[1];
    const float* W1   = (const float*)d_in[2];
    const float* as1  = (const float*)d_in[3];
    const float* ad1  = (const float*)d_in[4];
    const float* b1   = (const float*)d_in[5];
    const float* W2   = (const float*)d_in[6];
    const float* as2  = (const float*)d_in[7];
    const float* ad2  = (const float*)d_in[8];
    const float* b2   = (const float*)d_in[9];
    const float* fcw  = (const float*)d_in[10];
    const float* fcb  = (const float*)d_in[11];
    float* out = (float*)d_out;

    int N = in_sizes[0];          // x is [N, 1]
    int E = in_sizes[1] / 2;      // edge_index is [2, E]
    int Etot = E + N;             // + self loops
    const int* src = ei;
    const int* dst = ei + E;

    const int T = 256;
    k_zero   <<<1024, T>>>(N);
    k_l1_node<<<(N + T - 1) / T, T>>>(x, W1, as1, ad1, N);
    k_l1_edge<<<(Etot + T - 1) / T, T>>>(x, src, dst, E, Etot);
    k_l1_fin <<<(N * 32 + T - 1) / T, T>>>(W1, b1, N);
    k_l2_h2  <<<(N * 64 + T - 1) / T, T>>>(W2, N);
    k_l2_att <<<(N * 8 + T - 1) / T, T>>>(as2, ad2, N);
    k_l2_edge<<<((long)Etot * 8 + T - 1) / T, T>>>(src, dst, E, Etot);
    k_fin_fc <<<((long)N * 32 + T - 1) / T, T>>>(b2, fcw, fcb, out, N);
}